// round 6
// baseline (speedup 1.0000x reference)
#include <cuda_runtime.h>
#include <cstdint>

// ---------------- problem constants ----------------
#define NPTS   1000000
#define FX     512
#define FY     512
#define FZ     64
#define FIN    64
#define FH     32
#define SCORE_T 0.1f
#define CENT_T  0.2f
#define MAXP    128
#define CCAP    1024
#define BIN1_BASE 0x3E4Cu      // float_bits(0.2) >> 16 ; peak scores in (0.2, 1.0)
#define NBIN1  512
#define NBIN2  4096

// padded grid: [2][514][514][66], pad cells always 0
#define PX 514
#define PY 514
#define PZ 66
#define PCELLS (2*PX*PY*PZ)
#define DXS (PY*PZ)            // 33924
#define DYS (PZ)               // 66

// ---------------- device scratch (zero-init at module load) ----------------
__device__ unsigned int       g_grid[PCELLS];
__device__ int                g_cell[NPTS];     // packed coords (b<<24|x<<15|y<<6|z)
__device__ int                g_touch[NPTS];    // padded cells with s>0.1 (to reset)
__device__ unsigned long long g_cand[NPTS];     // s>0.2 candidates: (sb<<32)|~idx
__device__ int                g_ccellp[NPTS];   // padded cell per candidate
__device__ unsigned long long g_keys[NPTS];     // peaks
__device__ __align__(16) int  g_hist1[NBIN1];
__device__ int g_touch_count, g_cand_count, g_peak_count;

// ---------------- f32x2 helpers ----------------
__device__ __forceinline__ unsigned long long pk2(float x) {
    unsigned long long r; unsigned xi = __float_as_uint(x);
    asm("mov.b64 %0, {%1, %1};" : "=l"(r) : "r"(xi));
    return r;
}
__device__ __forceinline__ void fma2(unsigned long long& d, unsigned long long a, unsigned long long b) {
    asm("fma.rn.f32x2 %0, %1, %2, %0;" : "+l"(d) : "l"(a), "l"(b));
}
__device__ __forceinline__ float2 up2(unsigned long long v) {
    unsigned a, b;
    asm("mov.b64 {%0, %1}, %2;" : "=r"(a), "=r"(b) : "l"(v));
    return make_float2(__uint_as_float(a), __uint_as_float(b));
}

// ---------------- K1: MLP (f32x2, SMEM-staged coalesced feats) ----------------
#define FPAD 33   // row pitch in floats for staged features (bank-conflict-free)

__global__ void __launch_bounds__(256) k_mlp(
    const float* __restrict__ feats,
    const int*   __restrict__ cb, const int* __restrict__ cx,
    const int*   __restrict__ cy, const int* __restrict__ cz,
    const int*   __restrict__ mask,
    const float* __restrict__ W1, const float* __restrict__ b1,
    const float* __restrict__ W2, const float* __restrict__ b2,
    float* __restrict__ out_score)
{
    __shared__ __align__(16) float sW1[FIN * FH];   // 8 KB
    __shared__ __align__(16) float sb1[FH];
    __shared__ float sW2[FH];
    __shared__ float sb2;
    __shared__ float sF[256 * FPAD];                // 33 KB staged features

    int t = threadIdx.x;
    for (int i = t; i < FIN * FH; i += 256) sW1[i] = W1[i];
    if (t < FH) { sb1[t] = b1[t]; sW2[t] = W2[t]; }
    if (t == 0) sb2 = b2[0];

    int blockBase = blockIdx.x * 256;
    int i = blockBase + t;
    bool valid = (i < NPTS);

    const float4* F4 = reinterpret_cast<const float4*>(feats);

    unsigned long long acc[FH / 2];
    const unsigned long long* b1p = reinterpret_cast<const unsigned long long*>(sb1);

    // ---- stage chunk 0: features 0..31 (first 128B line of each point) ----
    #pragma unroll
    for (int u = 0; u < 8; u++) {
        int lin = u * 256 + t;          // 0..2047 float4 slots
        int p   = lin >> 3;             // local point 0..255
        int f4  = lin & 7;              // float4 index 0..7
        int gp  = blockBase + p; if (gp >= NPTS) gp = NPTS - 1;
        float4 v = F4[(size_t)gp * 16 + f4];
        float* dst = &sF[p * FPAD + f4 * 4];
        dst[0] = v.x; dst[1] = v.y; dst[2] = v.z; dst[3] = v.w;
    }
    __syncthreads();

    #pragma unroll
    for (int j = 0; j < FH / 2; j++) acc[j] = b1p[j];

    // ---- consume features 0..31 ----
    #pragma unroll 8
    for (int f = 0; f < 32; f++) {
        unsigned long long fp = pk2(sF[t * FPAD + f]);
        const ulonglong2* w = reinterpret_cast<const ulonglong2*>(&sW1[f * FH]);
        #pragma unroll
        for (int q = 0; q < FH / 4; q++) {
            ulonglong2 ww = w[q];
            fma2(acc[2 * q + 0], fp, ww.x);
            fma2(acc[2 * q + 1], fp, ww.y);
        }
    }
    __syncthreads();

    // ---- stage chunk 1: features 32..63 (second 128B line) ----
    #pragma unroll
    for (int u = 0; u < 8; u++) {
        int lin = u * 256 + t;
        int p   = lin >> 3;
        int f4  = lin & 7;
        int gp  = blockBase + p; if (gp >= NPTS) gp = NPTS - 1;
        float4 v = F4[(size_t)gp * 16 + 8 + f4];
        float* dst = &sF[p * FPAD + f4 * 4];
        dst[0] = v.x; dst[1] = v.y; dst[2] = v.z; dst[3] = v.w;
    }
    __syncthreads();

    // ---- consume features 32..63 ----
    #pragma unroll 8
    for (int f = 0; f < 32; f++) {
        unsigned long long fp = pk2(sF[t * FPAD + f]);
        const ulonglong2* w = reinterpret_cast<const ulonglong2*>(&sW1[(f + 32) * FH]);
        #pragma unroll
        for (int q = 0; q < FH / 4; q++) {
            ulonglong2 ww = w[q];
            fma2(acc[2 * q + 0], fp, ww.x);
            fma2(acc[2 * q + 1], fp, ww.y);
        }
    }

    float z = sb2;
    #pragma unroll
    for (int j = 0; j < FH / 2; j++) {
        float2 a = up2(acc[j]);
        z = fmaf(fmaxf(a.x, 0.0f), sW2[2 * j],     z);
        z = fmaf(fmaxf(a.y, 0.0f), sW2[2 * j + 1], z);
    }

    // ---- epilogue: score, scatter-max, touch & candidate lists ----
    float s = 0.0f;
    int cellp = 0;
    unsigned sb = 0u;
    if (valid) {
        s = 1.0f / (1.0f + expf(-z));
        if (mask[i] == 0) s = 0.0f;
        out_score[i] = s;
        int b = cb[i], x = cx[i], y = cy[i], zc = cz[i];
        g_cell[i] = (b << 24) | (x << 15) | (y << 6) | zc;
        cellp = ((b * PX + x + 1) * PY + y + 1) * PZ + (zc + 1);
        sb = __float_as_uint(s);
    }
    int lane = t & 31;

    bool dep = valid && (s > SCORE_T);
    if (dep) atomicMax(&g_grid[cellp], sb);
    unsigned m = __ballot_sync(0xFFFFFFFFu, dep);
    int base = 0;
    if (lane == 0 && m) base = atomicAdd(&g_touch_count, __popc(m));
    base = __shfl_sync(0xFFFFFFFFu, base, 0);
    if (dep) g_touch[base + __popc(m & ((1u << lane) - 1u))] = cellp;

    bool cnd = valid && (s > CENT_T);
    unsigned m2 = __ballot_sync(0xFFFFFFFFu, cnd);
    int base2 = 0;
    if (lane == 0 && m2) base2 = atomicAdd(&g_cand_count, __popc(m2));
    base2 = __shfl_sync(0xFFFFFFFFu, base2, 0);
    if (cnd) {
        int pos = base2 + __popc(m2 & ((1u << lane) - 1u));
        g_cand[pos]   = ((unsigned long long)sb << 32) | (unsigned)(~(unsigned)i);
        g_ccellp[pos] = cellp;
    }
}

// ---------------- K2: peak detect over candidate list ----------------
__global__ void __launch_bounds__(256) k_peak()
{
    int n   = g_cand_count;
    int gsz = gridDim.x * blockDim.x;
    int idx = blockIdx.x * blockDim.x + threadIdx.x;
    int iters = (n + gsz - 1) / gsz;
    int lane = threadIdx.x & 31;

    for (int it = 0; it < iters; it++, idx += gsz) {
        bool valid = (idx < n);
        unsigned long long key = 0ULL;
        unsigned sb = 0u, hmax = 0u;
        if (valid) {
            key = g_cand[idx];
            sb  = (unsigned)(key >> 32);
            int cp = g_ccellp[idx];
            #pragma unroll
            for (int dx = -1; dx <= 1; dx++) {
                #pragma unroll
                for (int dy = -1; dy <= 1; dy++) {
                    const unsigned* p = &g_grid[cp + dx * DXS + dy * DYS];
                    unsigned a = p[-1], b = p[0], c = p[1];
                    unsigned mx = a > b ? a : b;
                    mx = c > mx ? c : mx;
                    hmax = mx > hmax ? mx : hmax;
                }
            }
        }
        bool isPeak = valid && (hmax == sb);
        unsigned m = __ballot_sync(0xFFFFFFFFu, isPeak);
        int base = 0;
        if (lane == 0 && m) base = atomicAdd(&g_peak_count, __popc(m));
        base = __shfl_sync(0xFFFFFFFFu, base, 0);
        if (isPeak) {
            g_keys[base + __popc(m & ((1u << lane) - 1u))] = key;
            atomicAdd(&g_hist1[(sb >> 16) - BIN1_BASE], 1);
        }
    }
}

// ---------------- K3: cleanup grid via touch list (runs BEFORE k_topk) ----------------
__global__ void __launch_bounds__(256) k_cleanup()
{
    int tn  = g_touch_count;
    int gsz = gridDim.x * blockDim.x;
    for (int i = blockIdx.x * blockDim.x + threadIdx.x; i < tn; i += gsz)
        g_grid[g_touch[i]] = 0u;
}

// ---------------- K4: fused select + sort + emit + state reset (single block) --------
__global__ void __launch_bounds__(1024) k_topk(float* __restrict__ out)
{
    __shared__ int c1[NBIN1];
    __shared__ __align__(16) int h2[NBIN2];          // 16 KB
    __shared__ int csum[1024];
    __shared__ unsigned long long sk[CCAP];          // 8 KB
    __shared__ int sBin1, sAbove1;
    __shared__ unsigned int sThresh;
    __shared__ int sCnt;
    __shared__ int fill[MAXP];
    __shared__ int sValid;

    int t = threadIdx.x;
    int n = g_peak_count;
    if (t == 0) { sCnt = 0; sBin1 = -1; sAbove1 = 0; sThresh = 0u; }

    // ---- level-1 scan over 512 bins ----
    int h1 = (t < NBIN1) ? g_hist1[t] : 0;
    if (t < NBIN1) c1[t] = h1;
    __syncthreads();
    for (int off = 1; off < NBIN1; off <<= 1) {
        int v = (t < NBIN1 && t >= off) ? c1[t - off] : 0;
        __syncthreads();
        if (t < NBIN1) c1[t] += v;
        __syncthreads();
    }
    int total = c1[NBIN1 - 1];
    if (t < NBIN1 && total >= MAXP) {
        int above = total - c1[t];
        if (above < MAXP && above + h1 >= MAXP) { sBin1 = t; sAbove1 = above; }
    }
    // zero level-2 hist
    reinterpret_cast<int4*>(h2)[t] = make_int4(0, 0, 0, 0);
    __syncthreads();

    // ---- level-2 histogram (pass 1 over keys) ----
    int b1 = sBin1;
    if (b1 >= 0) {
        for (int i = t; i < n; i += 1024) {
            unsigned sb = (unsigned)(g_keys[i] >> 32);
            if ((int)((sb >> 16) - BIN1_BASE) == b1)
                atomicAdd(&h2[(sb >> 4) & 0xFFFu], 1);
        }
    }
    __syncthreads();

    // ---- level-2 scan (1024 threads x 4 bins) ----
    if (b1 >= 0) {
        int4 v = reinterpret_cast<const int4*>(h2)[t];
        int my = v.x + v.y + v.z + v.w;
        csum[t] = my;
        __syncthreads();
        for (int off = 1; off < 1024; off <<= 1) {
            int vv = (t >= off) ? csum[t - off] : 0;
            __syncthreads();
            csum[t] += vv;
            __syncthreads();
        }
        int tot2  = csum[1023];
        int above = sAbove1 + (tot2 - csum[t]);
        if (above < MAXP && above + my >= MAXP) {
            int run = above;
            int hh[4] = { v.x, v.y, v.z, v.w };
            #pragma unroll
            for (int b = 3; b >= 0; b--) {
                if (run + hh[b] >= MAXP) {
                    sThresh = ((unsigned)(b1 + BIN1_BASE) << 16) | ((unsigned)(t * 4 + b) << 4);
                    break;
                }
                run += hh[b];
            }
        }
        __syncthreads();
    }

    // ---- compact survivors (pass 2 over keys) ----
    unsigned th = sThresh;
    for (int i = t; i < n; i += 1024) {
        unsigned long long key = g_keys[i];
        if ((unsigned)(key >> 32) >= th) {
            int pos = atomicAdd(&sCnt, 1);
            if (pos < CCAP) sk[pos] = key;
        }
    }
    __syncthreads();
    int M = sCnt; if (M > CCAP) M = CCAP;
    if (t >= M) sk[t] = 0ULL;
    __syncthreads();

    // ---- bitonic sort, descending (1024 elems, 1/thread) ----
    for (int kk = 2; kk <= CCAP; kk <<= 1) {
        for (int j = kk >> 1; j > 0; j >>= 1) {
            int ixj = t ^ j;
            if (ixj > t) {
                unsigned long long a = sk[t], b = sk[ixj];
                bool desc = ((t & kk) == 0);
                if (desc ? (a < b) : (a > b)) { sk[t] = b; sk[ixj] = a; }
            }
            __syncthreads();
        }
    }

    // ---- fill path (practically never taken) ----
    if (t == 0) {
        int valid = M < MAXP ? M : MAXP;
        sValid = valid;
        if (valid < MAXP) {
            int need = MAXP - valid, got = 0;
            for (int i = 0; i < NPTS && got < need; i++) {
                bool isP = false;
                for (int q = 0; q < valid; q++) {
                    int pidx = (int)(~(unsigned)(sk[q] & 0xFFFFFFFFu));
                    if (pidx == i) { isP = true; break; }
                }
                if (!isP) { fill[valid + got] = i; got++; }
            }
        }
    }
    __syncthreads();

    // ---- emit outputs ----
    if (t < MAXP) {
        int valid = sValid;
        float sc; int idx;
        if (t < valid) {
            unsigned long long key = sk[t];
            sc  = __uint_as_float((unsigned)(key >> 32));
            idx = (int)(~(unsigned)(key & 0xFFFFFFFFu));
        } else {
            sc  = -1.0f;
            idx = fill[t];
        }
        out[NPTS + t]        = (float)idx;
        out[NPTS + MAXP + t] = sc;
        int cell = g_cell[idx];
        float* pc = out + NPTS + 2 * MAXP + (size_t)t * 4;
        pc[0] = (float)(cell >> 24);
        pc[1] = (float)((cell >> 15) & 511);
        pc[2] = (float)((cell >> 6) & 511);
        pc[3] = (float)(cell & 63);
    }

    // ---- reset global state for next replay (cleanup already consumed touch list) ----
    if (t < NBIN1) g_hist1[t] = 0;
    if (t == 0) { g_peak_count = 0; g_cand_count = 0; g_touch_count = 0; }
}

// ---------------- launch ----------------
extern "C" void kernel_launch(void* const* d_in, const int* in_sizes, int n_in,
                              void* d_out, int out_size) {
    const float* feats = (const float*)d_in[0];
    const int*   cb    = (const int*)  d_in[1];
    const int*   cx    = (const int*)  d_in[2];
    const int*   cy    = (const int*)  d_in[3];
    const int*   cz    = (const int*)  d_in[4];
    const int*   mask  = (const int*)  d_in[5];
    const float* W1    = (const float*)d_in[6];
    const float* b1    = (const float*)d_in[7];
    const float* W2    = (const float*)d_in[8];
    const float* b2    = (const float*)d_in[9];
    float* out = (float*)d_out;

    k_mlp<<<(NPTS + 255) / 256, 256>>>(feats, cb, cx, cy, cz, mask, W1, b1, W2, b2, out);
    k_peak<<<2048, 256>>>();
    k_cleanup<<<2048, 256>>>();
    k_topk<<<1, 1024>>>(out);
}